// round 3
// baseline (speedup 1.0000x reference)
#include <cuda_runtime.h>

// Problem constants (fixed by the dataset shapes)
#define B_      8
#define NHEADS  4
#define Q_      512      // codebook entries per head (N/4)
#define L_      2048     // sequence length (innermost logits dim)
#define D_      512      // embedding dim
#define K_      3        // top-k

#define LT       64      // l-tile per block
#define NTHREADS 256

// top-3 update, branch-light common path (v <= t2 almost always)
#define TOP3_UPDATE(v, n)                                              \
    do {                                                               \
        if ((v) > t2) {                                                \
            if ((v) > t0)      { t2=t1; i2=i1; t1=t0; i1=i0; t0=(v); i0=(n); } \
            else if ((v) > t1) { t2=t1; i2=i1; t1=(v); i1=(n); }       \
            else               { t2=(v); i2=(n); }                     \
        }                                                              \
    } while (0)

__global__ __launch_bounds__(NTHREADS)
void embed_topk_combine(const float* __restrict__ logits,
                        const float* __restrict__ e0,
                        const float* __restrict__ e1,
                        const float* __restrict__ e2,
                        const float* __restrict__ e3,
                        float* __restrict__ out)
{
    const int b   = blockIdx.y;
    const int l0  = blockIdx.x * LT;
    const int tid = threadIdx.x;

    __shared__ int   s_idx[NHEADS][LT][K_];
    __shared__ float s_w  [NHEADS][LT][K_];
    // 32 x (LT+1): column writes stride 65 ≡ 1 (mod 32) -> conflict-free
    __shared__ float tile[32][LT + 1];

    // ---------------- phase 1: top-3 + softmax per (h, l) ----------------
    {
        const int l = tid & (LT - 1);   // 0..63
        const int h = tid >> 6;         // 0..3
        const float* p = logits
            + ((size_t)b * (NHEADS * Q_) + (size_t)h * Q_) * L_ + l0 + l;

        float t0 = -3.4e38f, t1 = -3.4e38f, t2 = -3.4e38f;
        int   i0 = 0, i1 = 0, i2 = 0;

        // 4-wide explicit load batching: independent loads issue together,
        // compare chains consume them afterwards (MLP >= 4).
        for (int n = 0; n < Q_; n += 4) {
            float v0 = __ldg(p + (size_t)(n + 0) * L_);
            float v1 = __ldg(p + (size_t)(n + 1) * L_);
            float v2 = __ldg(p + (size_t)(n + 2) * L_);
            float v3 = __ldg(p + (size_t)(n + 3) * L_);
            TOP3_UPDATE(v0, n + 0);
            TOP3_UPDATE(v1, n + 1);
            TOP3_UPDATE(v2, n + 2);
            TOP3_UPDATE(v3, n + 3);
        }

        // softmax over the 3 kept values (t0 is the max)
        float w1  = expf(t1 - t0);
        float w2  = expf(t2 - t0);
        float inv = 1.0f / (1.0f + w1 + w2);
        s_w[h][l][0] = inv;
        s_w[h][l][1] = w1 * inv;
        s_w[h][l][2] = w2 * inv;
        s_idx[h][l][0] = i0;
        s_idx[h][l][1] = i1;
        s_idx[h][l][2] = i2;
    }
    __syncthreads();

    // ---------------- phase 2: weighted gather-combine + transpose -------
    const int warp = tid >> 5;
    const int lane = tid & 31;
    float* outb = out + (size_t)b * D_ * L_ + l0;

    for (int dd0 = 0; dd0 < D_; dd0 += 32) {
        // warp <-> l, lane <-> dd: every emb read is one coalesced 128B line
        for (int li = warp; li < LT; li += NTHREADS / 32) {
            float acc = 0.0f;
            #pragma unroll
            for (int h = 0; h < NHEADS; h++) {
                const float* eh = (h == 0) ? e0 : (h == 1) ? e1
                                 : (h == 2) ? e2 : e3;
                #pragma unroll
                for (int k = 0; k < K_; k++) {
                    int   m = s_idx[h][li][k];
                    float w = s_w  [h][li][k];
                    acc = fmaf(w, __ldg(eh + (size_t)m * D_ + dd0 + lane), acc);
                }
            }
            tile[lane][li] = acc;
        }
        __syncthreads();

        // coalesced store: consecutive tid -> consecutive l
        #pragma unroll
        for (int i = tid; i < 32 * LT; i += NTHREADS) {
            int ddl = i >> 6;        // i / LT   (LT == 64)
            int l   = i & (LT - 1);  // i % LT
            outb[(size_t)(dd0 + ddl) * L_ + l] = tile[ddl][l];
        }
        __syncthreads();
    }
}

extern "C" void kernel_launch(void* const* d_in, const int* in_sizes, int n_in,
                              void* d_out, int out_size)
{
    const float* logits = (const float*)d_in[0];
    const float* e0     = (const float*)d_in[1];
    const float* e1     = (const float*)d_in[2];
    const float* e2     = (const float*)d_in[3];
    const float* e3     = (const float*)d_in[4];
    float*       out    = (float*)d_out;

    dim3 grid(L_ / LT, B_);   // 32 x 8 = 256 blocks
    dim3 block(NTHREADS);
    embed_topk_combine<<<grid, block>>>(logits, e0, e1, e2, e3, out);
}

// round 4
// speedup vs baseline: 1.6986x; 1.6986x over previous
#include <cuda_runtime.h>

// Problem constants (fixed by the dataset shapes)
#define B_      8
#define NHEADS  4
#define Q_      512      // codebook entries per head (N/4)
#define L_      2048     // sequence length (innermost logits dim)
#define D_      512      // embedding dim
#define K_      3        // top-k

#define LT       32      // l-tile per block
#define NTHREADS 512
#define SEGS     4       // n-range split per (h,l)
#define NSEG     (Q_ / SEGS)   // 128

// top-3 update, branch-light common path (v <= t2 almost always)
#define TOP3_UPDATE(v, n)                                              \
    do {                                                               \
        if ((v) > t2) {                                                \
            if ((v) > t0)      { t2=t1; i2=i1; t1=t0; i1=i0; t0=(v); i0=(n); } \
            else if ((v) > t1) { t2=t1; i2=i1; t1=(v); i1=(n); }       \
            else               { t2=(v); i2=(n); }                     \
        }                                                              \
    } while (0)

__global__ __launch_bounds__(NTHREADS)
void embed_topk_combine(const float* __restrict__ logits,
                        const float* __restrict__ e0,
                        const float* __restrict__ e1,
                        const float* __restrict__ e2,
                        const float* __restrict__ e3,
                        float* __restrict__ out)
{
    const int b   = blockIdx.y;
    const int l0  = blockIdx.x * LT;
    const int tid = threadIdx.x;

    // partial top-3 from segments 1..3 (segment 0 stays in the merger's regs)
    __shared__ float s_pv [SEGS - 1][NHEADS][LT][K_];
    __shared__ int   s_pi [SEGS - 1][NHEADS][LT][K_];
    // merged result
    __shared__ int   s_idx[NHEADS][LT][K_];
    __shared__ float s_w  [NHEADS][LT][K_];
    // transpose tile: pitch 33 -> bank = (lane + li) mod 32, conflict-free
    __shared__ float tile[32][LT + 1];

    // ---------------- phase 1: split-n top-3 (MLP=8 per thread) ----------
    {
        const int l   = tid & (LT - 1);        // 0..31
        const int h   = (tid >> 5) & (NHEADS - 1); // 0..3
        const int seg = tid >> 7;              // 0..3
        const int nb  = seg * NSEG;

        const float* p = logits
            + ((size_t)b * (NHEADS * Q_) + (size_t)h * Q_ + nb) * L_ + l0 + l;

        float t0 = -3.4e38f, t1 = -3.4e38f, t2 = -3.4e38f;
        int   i0 = 0, i1 = 0, i2 = 0;

        // 8-wide load batching: 8 independent lines in flight per thread
        for (int n = 0; n < NSEG; n += 8) {
            float v0 = __ldg(p + (size_t)(n + 0) * L_);
            float v1 = __ldg(p + (size_t)(n + 1) * L_);
            float v2 = __ldg(p + (size_t)(n + 2) * L_);
            float v3 = __ldg(p + (size_t)(n + 3) * L_);
            float v4 = __ldg(p + (size_t)(n + 4) * L_);
            float v5 = __ldg(p + (size_t)(n + 5) * L_);
            float v6 = __ldg(p + (size_t)(n + 6) * L_);
            float v7 = __ldg(p + (size_t)(n + 7) * L_);
            TOP3_UPDATE(v0, nb + n + 0);
            TOP3_UPDATE(v1, nb + n + 1);
            TOP3_UPDATE(v2, nb + n + 2);
            TOP3_UPDATE(v3, nb + n + 3);
            TOP3_UPDATE(v4, nb + n + 4);
            TOP3_UPDATE(v5, nb + n + 5);
            TOP3_UPDATE(v6, nb + n + 6);
            TOP3_UPDATE(v7, nb + n + 7);
        }

        if (seg > 0) {
            s_pv[seg - 1][h][l][0] = t0;  s_pi[seg - 1][h][l][0] = i0;
            s_pv[seg - 1][h][l][1] = t1;  s_pi[seg - 1][h][l][1] = i1;
            s_pv[seg - 1][h][l][2] = t2;  s_pi[seg - 1][h][l][2] = i2;
        }
        __syncthreads();

        if (seg == 0) {
            // merge the 3 partials (each sorted desc) into this thread's top-3
            #pragma unroll
            for (int s = 0; s < SEGS - 1; s++) {
                #pragma unroll
                for (int k = 0; k < K_; k++) {
                    float v = s_pv[s][h][l][k];
                    int   n = s_pi[s][h][l][k];
                    TOP3_UPDATE(v, n);
                }
            }
            // softmax over the 3 kept values (t0 is the max)
            float w1  = expf(t1 - t0);
            float w2  = expf(t2 - t0);
            float inv = 1.0f / (1.0f + w1 + w2);
            s_w[h][l][0] = inv;
            s_w[h][l][1] = w1 * inv;
            s_w[h][l][2] = w2 * inv;
            s_idx[h][l][0] = i0;
            s_idx[h][l][1] = i1;
            s_idx[h][l][2] = i2;
        }
    }
    __syncthreads();

    // ---------------- phase 2: weighted gather-combine + transpose -------
    const int warp = tid >> 5;   // 0..15
    const int lane = tid & 31;
    float* outb = out + (size_t)b * D_ * L_ + l0;

    for (int dd0 = 0; dd0 < D_; dd0 += 32) {
        // warp <-> l, lane <-> dd: each emb read is one coalesced 128B line,
        // rows repeat across li within the block -> L1 hits
        #pragma unroll
        for (int li = warp; li < LT; li += NTHREADS / 32) {
            float acc = 0.0f;
            #pragma unroll
            for (int h = 0; h < NHEADS; h++) {
                const float* eh = (h == 0) ? e0 : (h == 1) ? e1
                                 : (h == 2) ? e2 : e3;
                #pragma unroll
                for (int k = 0; k < K_; k++) {
                    int   m = s_idx[h][li][k];
                    float w = s_w  [h][li][k];
                    acc = fmaf(w, __ldg(eh + (size_t)m * D_ + dd0 + lane), acc);
                }
            }
            tile[lane][li] = acc;
        }
        __syncthreads();

        // coalesced store: consecutive tid -> consecutive l
        #pragma unroll
        for (int i = tid; i < 32 * LT; i += NTHREADS) {
            int ddl = i >> 5;        // i / LT   (LT == 32)
            int l   = i & (LT - 1);  // i % LT
            outb[(size_t)(dd0 + ddl) * L_ + l] = tile[ddl][l];
        }
        __syncthreads();
    }
}

extern "C" void kernel_launch(void* const* d_in, const int* in_sizes, int n_in,
                              void* d_out, int out_size)
{
    const float* logits = (const float*)d_in[0];
    const float* e0     = (const float*)d_in[1];
    const float* e1     = (const float*)d_in[2];
    const float* e2     = (const float*)d_in[3];
    const float* e3     = (const float*)d_in[4];
    float*       out    = (float*)d_out;

    dim3 grid(L_ / LT, B_);   // 64 x 8 = 512 blocks
    dim3 block(NTHREADS);
    embed_topk_combine<<<grid, block>>>(logits, e0, e1, e2, e3, out);
}